// round 4
// baseline (speedup 1.0000x reference)
#include <cuda_runtime.h>

// GroupQueryAttention: B=2, S=2048, E=768, H=12, G=4, D=64, T=512
// Round 1: resubmit of round-0 fp32 baseline (round-0 bench died to infra).
// Linear stages use packed fma.rn.f32x2 (FFMA2); attention is a fused
// flash-softmax kernel in plain fp32.
//
// Input order (metadata):
//  0 query [B,S,E]   1 key [B,S,E]   2 value [B,S,E]
//  3 Wqg [E,E] 4 bqg [E]  5 Wk [E,E] 6 bk [E]  7 Wv [E,E] 8 bv [E]
//  9 Wq_in [G,E,E] 10 bq_in [G,E] 11 Wk_in 12 bk_in 13 Wv_in 14 bv_in
// 15 Wout [G,E,E] 16 bout [G,E]

typedef unsigned long long ull;

constexpr int kE = 768;
constexpr int kB = 2;
constexpr int kS = 2048;
constexpr int kH = 12;
constexpr int kG = 4;
constexpr int kD = 64;
constexpr int kT = 512;   // S / G

// ---------------- scratch (device globals; no allocations allowed) ----------
__device__ float g_q  [kB * kS * kE];           // outer q projection
__device__ float g_k  [kB * kS * kE];           // outer k projection
__device__ float g_v  [kB * kS * kE];           // outer v projection
__device__ float g_qi [kB * kG * kT * kE];      // per-group q in-proj [b,g,t,e]
__device__ float g_ki [kB * kG * kS * kE];      // per-group k in-proj [b,g,s,e]
__device__ float g_vi [kB * kG * kS * kE];      // per-group v in-proj [b,g,s,e]
__device__ float g_ctx[kB * kG * kT * kE];      // attention context  [b,g,t,e]

// ---------------- f32x2 helpers ---------------------------------------------
__device__ __forceinline__ ull pack2(float lo, float hi) {
    ull r;
    asm("mov.b64 %0, {%1, %2};" : "=l"(r) : "f"(lo), "f"(hi));
    return r;
}
__device__ __forceinline__ void unpack2(ull v, float& lo, float& hi) {
    asm("mov.b64 {%0, %1}, %2;" : "=f"(lo), "=f"(hi) : "l"(v));
}
__device__ __forceinline__ void ffma2(ull& acc, ull a, ull b) {
    asm("fma.rn.f32x2 %0, %1, %2, %0;" : "+l"(acc) : "l"(a), "l"(b));
}

// ---------------- GEMM: C[M,768] = gather(A)[M,768] @ W_g[768,768]^T + b_g ---
// MODE 0: plain rows, single weight (outer projections)
// MODE 1: qi -- A rows gathered with the interleaved-group permutation,
//              weight/bias selected by group g; row m = ((b*G+g)*T + t)
// MODE 2: ki/vi -- A row = b*S + s (k broadcast over groups); m = ((b*G+g)*S+s)
// MODE 3: out-proj -- A rows 1:1, OUTPUT rows scattered back to sequence order
template <int MODE>
__device__ __forceinline__ int in_row(int m) {
    if (MODE == 1) {
        int b = m >> 11;          // / (G*T) = 2048
        int g = (m >> 9) & 3;     // / T     = 512
        int t = m & 511;
        return (b << 11) + (t << 2) + g;   // b*S + t*G + g
    }
    if (MODE == 2) {
        int b = m >> 13;          // / (G*S) = 8192
        int s = m & 2047;
        return (b << 11) + s;     // b*S + s
    }
    return m;
}
__device__ __forceinline__ int perm_row(int m) {   // (b,g,t) -> b*S + t*G + g
    int b = m >> 11;
    int g = (m >> 9) & 3;
    int t = m & 511;
    return (b << 11) + (t << 2) + g;
}

template <int MODE>
__global__ __launch_bounds__(256, 2)
void gemm_kernel(const float* __restrict__ A, const float* __restrict__ W,
                 const float* __restrict__ bias, float* __restrict__ C) {
    __shared__ float As[16][132];
    __shared__ float Bs[16][132];

    const int tid = threadIdx.x;
    const int m0 = blockIdx.y * 128;
    const int n0 = blockIdx.x * 128;

    int g = 0;
    if (MODE == 1 || MODE == 3) g = (m0 >> 9) & 3;
    if (MODE == 2)              g = (m0 >> 11) & 3;

    const float* Wg = W + (size_t)g * kE * kE;
    const float* bg = bias + (size_t)g * kE;

    const int lr = tid >> 2;          // 0..63
    const int lc = (tid & 3) * 4;     // 0,4,8,12

    const int ar0 = in_row<MODE>(m0 + lr);
    const int ar1 = in_row<MODE>(m0 + lr + 64);
    const float* Ap0 = A  + (size_t)ar0 * kE + lc;
    const float* Ap1 = A  + (size_t)ar1 * kE + lc;
    const float* Wp0 = Wg + (size_t)(n0 + lr) * kE + lc;
    const float* Wp1 = Wg + (size_t)(n0 + lr + 64) * kE + lc;

    const int tr = tid >> 4;          // 0..15 -> rows tr*8..tr*8+7
    const int tc = tid & 15;          // 0..15 -> cols tc*8..tc*8+7

    // bias for this thread's 8 output columns (hoisted; global, L2-resident)
    float bv[8];
#pragma unroll
    for (int j = 0; j < 8; j++) bv[j] = bg[n0 + tc * 8 + j];

    ull acc[8][4];
#pragma unroll
    for (int i = 0; i < 8; i++)
#pragma unroll
        for (int j = 0; j < 4; j++) acc[i][j] = 0ull;

    for (int k0 = 0; k0 < kE; k0 += 16) {
        const float4 a0 = *(const float4*)(Ap0 + k0);
        const float4 a1 = *(const float4*)(Ap1 + k0);
        const float4 w0 = *(const float4*)(Wp0 + k0);
        const float4 w1 = *(const float4*)(Wp1 + k0);
        __syncthreads();
        As[lc + 0][lr] = a0.x; As[lc + 1][lr] = a0.y;
        As[lc + 2][lr] = a0.z; As[lc + 3][lr] = a0.w;
        As[lc + 0][lr + 64] = a1.x; As[lc + 1][lr + 64] = a1.y;
        As[lc + 2][lr + 64] = a1.z; As[lc + 3][lr + 64] = a1.w;
        Bs[lc + 0][lr] = w0.x; Bs[lc + 1][lr] = w0.y;
        Bs[lc + 2][lr] = w0.z; Bs[lc + 3][lr] = w0.w;
        Bs[lc + 0][lr + 64] = w1.x; Bs[lc + 1][lr + 64] = w1.y;
        Bs[lc + 2][lr + 64] = w1.z; Bs[lc + 3][lr + 64] = w1.w;
        __syncthreads();

#pragma unroll
        for (int k = 0; k < 16; k++) {
            const float4 qa0 = *(const float4*)&As[k][tr * 8];
            const float4 qa1 = *(const float4*)&As[k][tr * 8 + 4];
            const float4 qb0 = *(const float4*)&Bs[k][tc * 8];
            const float4 qb1 = *(const float4*)&Bs[k][tc * 8 + 4];
            ull aa[8];
            aa[0] = pack2(qa0.x, qa0.x); aa[1] = pack2(qa0.y, qa0.y);
            aa[2] = pack2(qa0.z, qa0.z); aa[3] = pack2(qa0.w, qa0.w);
            aa[4] = pack2(qa1.x, qa1.x); aa[5] = pack2(qa1.y, qa1.y);
            aa[6] = pack2(qa1.z, qa1.z); aa[7] = pack2(qa1.w, qa1.w);
            ull bb[4];
            bb[0] = pack2(qb0.x, qb0.y); bb[1] = pack2(qb0.z, qb0.w);
            bb[2] = pack2(qb1.x, qb1.y); bb[3] = pack2(qb1.z, qb1.w);
#pragma unroll
            for (int i = 0; i < 8; i++)
#pragma unroll
                for (int j = 0; j < 4; j++) ffma2(acc[i][j], aa[i], bb[j]);
        }
    }

#pragma unroll
    for (int i = 0; i < 8; i++) {
        const int m = m0 + tr * 8 + i;
        const size_t orow = (MODE == 3) ? (size_t)perm_row(m) : (size_t)m;
        float* crow = C + orow * kE + n0 + tc * 8;
#pragma unroll
        for (int j = 0; j < 4; j++) {
            float lo, hi;
            unpack2(acc[i][j], lo, hi);
            *(float2*)(crow + 2 * j) = make_float2(lo + bv[2 * j], hi + bv[2 * j + 1]);
        }
    }
}

// ---------------- fused flash attention -------------------------------------
// grid: (T/128, B*G*H). Block: 256 threads (16x16), BQ=128, BKV=64, D=64.
// smem: Qs[d][r] 64x132 | Ks[d][c] 64x68 | Vs[s][d] 64x68 | Ps[r][c] 128x68
__global__ __launch_bounds__(256, 2)
void attn_kernel() {
    extern __shared__ float sm[];
    float* sQ = sm;                    // 64*132 = 8448
    float* sK = sQ + 64 * 132;         // 64*68  = 4352
    float* sV = sK + 64 * 68;          // 64*68  = 4352
    float* sP = sV + 64 * 68;          // 128*68 = 8704

    const int tid = threadIdx.x;
    const int y = blockIdx.y;
    const int b = y / (kG * kH);
    const int g = (y / kH) & 3;
    const int h = y % kH;
    const int q0 = blockIdx.x * 128;

    const size_t head_q  = ((size_t)(b * kG + g) * kT) * kE + h * kD;
    const size_t head_kv = ((size_t)(b * kG + g) * kS) * kE + h * kD;

    // load Q tile transposed, pre-scaled by 1/sqrt(D)=0.125
#pragma unroll
    for (int it = 0; it < 8; ++it) {
        const int idx = tid + 256 * it;
        const int r = idx >> 4;
        const int d4 = (idx & 15) * 4;
        const float4 q4 = *(const float4*)(g_qi + head_q + (size_t)(q0 + r) * kE + d4);
        sQ[(d4 + 0) * 132 + r] = q4.x * 0.125f;
        sQ[(d4 + 1) * 132 + r] = q4.y * 0.125f;
        sQ[(d4 + 2) * 132 + r] = q4.z * 0.125f;
        sQ[(d4 + 3) * 132 + r] = q4.w * 0.125f;
    }

    const int tr = tid >> 4;   // rows tr*8 .. tr*8+7
    const int tc = tid & 15;   // score cols / O d-cols tc*4 .. tc*4+3

    float m_i[8], l_i[8], o[8][4];
#pragma unroll
    for (int i = 0; i < 8; i++) {
        m_i[i] = -1e30f;
        l_i[i] = 0.f;
#pragma unroll
        for (int j = 0; j < 4; j++) o[i][j] = 0.f;
    }

    for (int kv = 0; kv < kS; kv += 64) {
        __syncthreads();   // prior tile's smem fully consumed
        // load K (transposed) and V tiles
#pragma unroll
        for (int it = 0; it < 4; ++it) {
            const int idx = tid + 256 * it;
            const int s = idx >> 4;
            const int d4 = (idx & 15) * 4;
            const float4 k4 = *(const float4*)(g_ki + head_kv + (size_t)(kv + s) * kE + d4);
            sK[(d4 + 0) * 68 + s] = k4.x;
            sK[(d4 + 1) * 68 + s] = k4.y;
            sK[(d4 + 2) * 68 + s] = k4.z;
            sK[(d4 + 3) * 68 + s] = k4.w;
            const float4 v4 = *(const float4*)(g_vi + head_kv + (size_t)(kv + s) * kE + d4);
            *(float4*)&sV[s * 68 + d4] = v4;
        }
        __syncthreads();

        // scores: [128 x 64] = Q^T-tile . K-tile over d
        float acc[8][4];
#pragma unroll
        for (int i = 0; i < 8; i++)
#pragma unroll
            for (int j = 0; j < 4; j++) acc[i][j] = 0.f;

#pragma unroll 4
        for (int d = 0; d < 64; ++d) {
            const float4 a0 = *(const float4*)&sQ[d * 132 + tr * 8];
            const float4 a1 = *(const float4*)&sQ[d * 132 + tr * 8 + 4];
            const float4 kb = *(const float4*)&sK[d * 68 + tc * 4];
            const float av[8] = {a0.x, a0.y, a0.z, a0.w, a1.x, a1.y, a1.z, a1.w};
#pragma unroll
            for (int i = 0; i < 8; i++) {
                acc[i][0] += av[i] * kb.x;
                acc[i][1] += av[i] * kb.y;
                acc[i][2] += av[i] * kb.z;
                acc[i][3] += av[i] * kb.w;
            }
        }

        // online softmax (row stats across 16 consecutive lanes)
#pragma unroll
        for (int i = 0; i < 8; i++) {
            float mt = fmaxf(fmaxf(acc[i][0], acc[i][1]), fmaxf(acc[i][2], acc[i][3]));
            mt = fmaxf(mt, __shfl_xor_sync(0xffffffffu, mt, 1));
            mt = fmaxf(mt, __shfl_xor_sync(0xffffffffu, mt, 2));
            mt = fmaxf(mt, __shfl_xor_sync(0xffffffffu, mt, 4));
            mt = fmaxf(mt, __shfl_xor_sync(0xffffffffu, mt, 8));
            const float mnew = fmaxf(m_i[i], mt);
            const float corr = __expf(m_i[i] - mnew);
            const float p0 = __expf(acc[i][0] - mnew);
            const float p1 = __expf(acc[i][1] - mnew);
            const float p2 = __expf(acc[i][2] - mnew);
            const float p3 = __expf(acc[i][3] - mnew);
            float rs = (p0 + p1) + (p2 + p3);
            rs += __shfl_xor_sync(0xffffffffu, rs, 1);
            rs += __shfl_xor_sync(0xffffffffu, rs, 2);
            rs += __shfl_xor_sync(0xffffffffu, rs, 4);
            rs += __shfl_xor_sync(0xffffffffu, rs, 8);
            l_i[i] = l_i[i] * corr + rs;
            m_i[i] = mnew;
            o[i][0] *= corr; o[i][1] *= corr; o[i][2] *= corr; o[i][3] *= corr;
            *(float4*)&sP[(tr * 8 + i) * 68 + tc * 4] = make_float4(p0, p1, p2, p3);
        }
        __syncthreads();   // P tile complete before cross-thread read

        // O += P . V
#pragma unroll 1
        for (int s4 = 0; s4 < 64; s4 += 4) {
            float4 pv[8];
#pragma unroll
            for (int i = 0; i < 8; i++)
                pv[i] = *(const float4*)&sP[(tr * 8 + i) * 68 + s4];
#pragma unroll
            for (int u = 0; u < 4; u++) {
                const float4 vb = *(const float4*)&sV[(s4 + u) * 68 + tc * 4];
#pragma unroll
                for (int i = 0; i < 8; i++) {
                    const float p = (u == 0) ? pv[i].x : (u == 1) ? pv[i].y
                                  : (u == 2) ? pv[i].z : pv[i].w;
                    o[i][0] += p * vb.x;
                    o[i][1] += p * vb.y;
                    o[i][2] += p * vb.z;
                    o[i][3] += p * vb.w;
                }
            }
        }
    }

    // epilogue: normalize and write ctx
#pragma unroll
    for (int i = 0; i < 8; i++) {
        const float inv = 1.0f / l_i[i];
        const float4 r4 = make_float4(o[i][0] * inv, o[i][1] * inv,
                                      o[i][2] * inv, o[i][3] * inv);
        *(float4*)(g_ctx + head_q + (size_t)(q0 + tr * 8 + i) * kE + tc * 4) = r4;
    }
}

// ---------------- launch ----------------------------------------------------
extern "C" void kernel_launch(void* const* d_in, const int* in_sizes, int n_in,
                              void* d_out, int out_size) {
    const float* query = (const float*)d_in[0];
    const float* key   = (const float*)d_in[1];
    const float* value = (const float*)d_in[2];
    const float* Wqg   = (const float*)d_in[3];
    const float* bqg   = (const float*)d_in[4];
    const float* Wk    = (const float*)d_in[5];
    const float* bk    = (const float*)d_in[6];
    const float* Wv    = (const float*)d_in[7];
    const float* bv    = (const float*)d_in[8];
    const float* Wq_in = (const float*)d_in[9];
    const float* bq_in = (const float*)d_in[10];
    const float* Wk_in = (const float*)d_in[11];
    const float* bk_in = (const float*)d_in[12];
    const float* Wv_in = (const float*)d_in[13];
    const float* bv_in = (const float*)d_in[14];
    const float* Wout  = (const float*)d_in[15];
    const float* bout  = (const float*)d_in[16];

    void *pq, *pk, *pv, *pqi, *pki, *pvi, *pctx;
    cudaGetSymbolAddress(&pq, g_q);
    cudaGetSymbolAddress(&pk, g_k);
    cudaGetSymbolAddress(&pv, g_v);
    cudaGetSymbolAddress(&pqi, g_qi);
    cudaGetSymbolAddress(&pki, g_ki);
    cudaGetSymbolAddress(&pvi, g_vi);
    cudaGetSymbolAddress(&pctx, g_ctx);

    const int smem_attn = (64 * 132 + 64 * 68 + 64 * 68 + 128 * 68) * 4;  // 103424 B
    cudaFuncSetAttribute(attn_kernel, cudaFuncAttributeMaxDynamicSharedMemorySize,
                         smem_attn);

    const dim3 blk(256);
    // outer projections
    gemm_kernel<0><<<dim3(6, 32), blk>>>(query, Wqg, bqg, (float*)pq);
    gemm_kernel<0><<<dim3(6, 32), blk>>>(key,   Wk,  bk,  (float*)pk);
    gemm_kernel<0><<<dim3(6, 32), blk>>>(value, Wv,  bv,  (float*)pv);
    // per-group in-projections
    gemm_kernel<1><<<dim3(6, 32),  blk>>>((const float*)pq, Wq_in, bq_in, (float*)pqi);
    gemm_kernel<2><<<dim3(6, 128), blk>>>((const float*)pk, Wk_in, bk_in, (float*)pki);
    gemm_kernel<2><<<dim3(6, 128), blk>>>((const float*)pv, Wv_in, bv_in, (float*)pvi);
    // fused flash attention over all (b,g,h)
    attn_kernel<<<dim3(kT / 128, kB * kG * kH), blk, smem_attn>>>();
    // out-projection with scatter back to sequence order
    gemm_kernel<3><<<dim3(6, 32), blk>>>((const float*)pctx, Wout, bout, (float*)d_out);
}

// round 6
// speedup vs baseline: 1.5670x; 1.5670x over previous
#include <cuda_runtime.h>
#include <cuda_bf16.h>
#include <cstdint>

// GroupQueryAttention: B=2, S=2048, E=768, H=12, G=4, D=64, T=512
// Round 6: bf16x3 split-precision GEMMs on mma.sync (HMMA, base PTX — the
// harness compiles PTX at compute_103, so tcgen05 is unavailable).
// fp32 flash attention unchanged (known good).

constexpr int kE = 768;
constexpr int kB = 2;
constexpr int kS = 2048;
constexpr int kH = 12;
constexpr int kG = 4;
constexpr int kD = 64;
constexpr int kT = 512;                 // S / G
constexpr int kNSE = kB * kS * kE;      // 3,145,728
constexpr int kEE  = kE * kE;           // 589,824
constexpr int kGEE = kG * kE * kE;      // 2,359,296
constexpr int kGSE = kB * kG * kS * kE; // 12,582,912

// ---------------- scratch (device globals; no allocations allowed) ----------
__device__ float g_qi[kB * kG * kT * kE];   // fp32 attention inputs
__device__ float g_ki[kGSE];
__device__ float g_vi[kGSE];

// hi/lo bf16 decompositions
__device__ __nv_bfloat16 c_q_h[kNSE], c_q_l[kNSE];   // query input
__device__ __nv_bfloat16 c_k_h[kNSE], c_k_l[kNSE];   // key input
__device__ __nv_bfloat16 c_v_h[kNSE], c_v_l[kNSE];   // value input
__device__ __nv_bfloat16 a_q_h[kNSE], a_q_l[kNSE];   // outer q proj
__device__ __nv_bfloat16 a_k_h[kNSE], a_k_l[kNSE];   // outer k proj
__device__ __nv_bfloat16 a_x_h[kNSE], a_x_l[kNSE];   // outer v proj
__device__ __nv_bfloat16 a_c_h[kNSE], a_c_l[kNSE];   // attn context [b,g,t,e]
__device__ __nv_bfloat16 w0_h[kEE],  w0_l[kEE];      // Wqg
__device__ __nv_bfloat16 w1_h[kEE],  w1_l[kEE];      // Wk
__device__ __nv_bfloat16 w2_h[kEE],  w2_l[kEE];      // Wv
__device__ __nv_bfloat16 wq_h[kGEE], wq_l[kGEE];     // Wq_in
__device__ __nv_bfloat16 wk_h[kGEE], wk_l[kGEE];     // Wk_in
__device__ __nv_bfloat16 wv_h[kGEE], wv_l[kGEE];     // Wv_in
__device__ __nv_bfloat16 wo_h[kGEE], wo_l[kGEE];     // Wout

// ---------------- helpers ----------------------------------------------------
__device__ __forceinline__ uint32_t smem_u32(const void* p) {
    uint32_t a;
    asm("{ .reg .u64 t; cvta.to.shared.u64 t, %1; cvt.u32.u64 %0, t; }"
        : "=r"(a) : "l"(p));
    return a;
}
__device__ __forceinline__ uint32_t lds32(uint32_t a) {
    uint32_t v;
    asm volatile("ld.shared.b32 %0, [%1];" : "=r"(v) : "r"(a));
    return v;
}
__device__ __forceinline__ void cp16(uint32_t dst, const void* src) {
    asm volatile("cp.async.cg.shared.global [%0], [%1], 16;" :: "r"(dst), "l"(src));
}
#define CP_COMMIT() asm volatile("cp.async.commit_group;" ::: "memory")
#define CP_WAIT0()  asm volatile("cp.async.wait_group 0;" ::: "memory")

__device__ __forceinline__ void mma_bf16(float* c, const uint32_t* a, const uint32_t* b) {
    asm volatile(
        "mma.sync.aligned.m16n8k16.row.col.f32.bf16.bf16.f32 "
        "{%0,%1,%2,%3}, {%4,%5,%6,%7}, {%8,%9}, {%0,%1,%2,%3};"
        : "+f"(c[0]), "+f"(c[1]), "+f"(c[2]), "+f"(c[3])
        : "r"(a[0]), "r"(a[1]), "r"(a[2]), "r"(a[3]), "r"(b[0]), "r"(b[1]));
}

__device__ __forceinline__ void split1(float x, __nv_bfloat16& h, __nv_bfloat16& l) {
    h = __float2bfloat16(x);
    l = __float2bfloat16(x - __bfloat162float(h));
}
__device__ __forceinline__ uint32_t pk(__nv_bfloat16 a, __nv_bfloat16 b) {
    uint16_t ua = *(uint16_t*)&a, ub = *(uint16_t*)&b;
    return (uint32_t)ua | ((uint32_t)ub << 16);
}

// ---------------- row mappings -----------------------------------------------
template <int MODE>
__device__ __forceinline__ int in_row(int m) {
    if (MODE == 1) {
        int b = m >> 11; int g = (m >> 9) & 3; int t = m & 511;
        return (b << 11) + (t << 2) + g;
    }
    if (MODE == 2) {
        int b = m >> 13; int s = m & 2047;
        return (b << 11) + s;
    }
    return m;
}
__device__ __forceinline__ int perm_row(int m) {
    int b = m >> 11; int g = (m >> 9) & 3; int t = m & 511;
    return (b << 11) + (t << 2) + g;
}

// ---------------- hi/lo conversion kernel ------------------------------------
__global__ void cvt_hl(const float4* __restrict__ in, uint2* __restrict__ h,
                       uint2* __restrict__ l, int n4) {
    int i = blockIdx.x * 256 + threadIdx.x;
    if (i >= n4) return;
    float4 v = in[i];
    __nv_bfloat16 h0, l0, h1, l1, h2, l2, h3, l3;
    split1(v.x, h0, l0); split1(v.y, h1, l1);
    split1(v.z, h2, l2); split1(v.w, h3, l3);
    h[i] = make_uint2(pk(h0, h1), pk(h2, h3));
    l[i] = make_uint2(pk(l0, l1), pk(l2, l3));
}

// ---------------- bf16x3 HMMA GEMM -------------------------------------------
// C[M,768] = gather(A)[M,768] @ W_g[768,768]^T + b_g.
// CTA tile 128x128; 8 warps (4x2), warp tile 32x64. K panels of 32,
// cp.async double-buffered. smem rows padded to stride 40 bf16 (bank-clean).
constexpr int PSTR = 40;               // padded row stride (bf16 elems)
constexpr int MATB = 128 * PSTR * 2;   // 10240 B per matrix
constexpr int BUFB = 4 * MATB;         // 40960 B per buffer (Ah|Al|Wh|Wl)
constexpr int kSmemGemm = 2 * BUFB;    // 81920 B

template <int MODE, bool HL>
__global__ __launch_bounds__(256, 2)
void gemm_mma(const __nv_bfloat16* __restrict__ Ah, const __nv_bfloat16* __restrict__ Al,
              const __nv_bfloat16* __restrict__ Wh, const __nv_bfloat16* __restrict__ Wl,
              const float* __restrict__ bias, float* __restrict__ outF,
              __nv_bfloat16* __restrict__ outH, __nv_bfloat16* __restrict__ outL) {
    extern __shared__ char s_raw[];
    const uint32_t sb = smem_u32(s_raw);

    const int tid = threadIdx.x;
    const int m0 = blockIdx.y * 128;
    const int n0 = blockIdx.x * 128;

    int g = 0;
    if (MODE == 1 || MODE == 3) g = (m0 >> 9) & 3;
    if (MODE == 2)              g = (m0 >> 11) & 3;
    const __nv_bfloat16* WgH = Wh + (size_t)g * kEE;
    const __nv_bfloat16* WgL = Wl + (size_t)g * kEE;
    const float* bg = bias + (size_t)g * kE;

    // panel-load addressing: 2 threads per row, 16 elems per half
    const int lrow = tid >> 1;
    const int lhalf = tid & 1;
    const int arow = in_row<MODE>(m0 + lrow);
    const __nv_bfloat16* pAh = Ah  + (size_t)arow * kE + lhalf * 16;
    const __nv_bfloat16* pAl = Al  + (size_t)arow * kE + lhalf * 16;
    const __nv_bfloat16* pWh = WgH + (size_t)(n0 + lrow) * kE + lhalf * 16;
    const __nv_bfloat16* pWl = WgL + (size_t)(n0 + lrow) * kE + lhalf * 16;
    const uint32_t sdst = sb + (uint32_t)(lrow * PSTR + lhalf * 16) * 2;

    const int lane = tid & 31;
    const int wid = tid >> 5;
    const int r0 = (wid & 3) * 32;        // warp row base
    const int c0 = (wid >> 2) * 64;       // warp col base
    const int lr = lane >> 2;             // 0..7
    const int lq = lane & 3;              // 0..3

    float acc[2][8][4];
#pragma unroll
    for (int i = 0; i < 2; i++)
#pragma unroll
        for (int j = 0; j < 8; j++)
#pragma unroll
            for (int q = 0; q < 4; q++) acc[i][j][q] = 0.f;

    // issue panel 0
    {
        const int go = 0;
        cp16(sdst,                 pAh + go); cp16(sdst + 16,                 pAh + go + 8);
        cp16(sdst + MATB,          pAl + go); cp16(sdst + MATB + 16,          pAl + go + 8);
        cp16(sdst + 2 * MATB,      pWh + go); cp16(sdst + 2 * MATB + 16,      pWh + go + 8);
        cp16(sdst + 3 * MATB,      pWl + go); cp16(sdst + 3 * MATB + 16,      pWl + go + 8);
        CP_COMMIT();
    }

#pragma unroll 1
    for (int p = 0; p < 24; ++p) {
        CP_WAIT0();
        __syncthreads();
        if (p + 1 < 24) {
            const int go = (p + 1) * 32;
            const uint32_t d = sdst + ((p + 1) & 1) * BUFB;
            cp16(d,                 pAh + go); cp16(d + 16,                 pAh + go + 8);
            cp16(d + MATB,          pAl + go); cp16(d + MATB + 16,          pAl + go + 8);
            cp16(d + 2 * MATB,      pWh + go); cp16(d + 2 * MATB + 16,      pWh + go + 8);
            cp16(d + 3 * MATB,      pWl + go); cp16(d + 3 * MATB + 16,      pWl + go + 8);
            CP_COMMIT();
        }

        const uint32_t bbase = sb + (p & 1) * BUFB;
#pragma unroll
        for (int ks = 0; ks < 2; ++ks) {
            const uint32_t kofs = (uint32_t)(ks * 16 + lq * 2) * 2;
            uint32_t AhF[2][4], AlF[2][4], BF[8][2];
#pragma unroll
            for (int i = 0; i < 2; i++) {
                const uint32_t ab = bbase + (uint32_t)((r0 + i * 16 + lr) * PSTR) * 2 + kofs;
                AhF[i][0] = lds32(ab);
                AhF[i][1] = lds32(ab + 8 * PSTR * 2);
                AhF[i][2] = lds32(ab + 16);
                AhF[i][3] = lds32(ab + 8 * PSTR * 2 + 16);
                const uint32_t al = ab + MATB;
                AlF[i][0] = lds32(al);
                AlF[i][1] = lds32(al + 8 * PSTR * 2);
                AlF[i][2] = lds32(al + 16);
                AlF[i][3] = lds32(al + 8 * PSTR * 2 + 16);
            }
#pragma unroll
            for (int j = 0; j < 8; j++) {
                const uint32_t nb = bbase + 2 * MATB
                                  + (uint32_t)((c0 + j * 8 + lr) * PSTR) * 2 + kofs;
                BF[j][0] = lds32(nb);
                BF[j][1] = lds32(nb + 16);
            }
#pragma unroll
            for (int j = 0; j < 8; j++) {
                mma_bf16(acc[0][j], AhF[0], BF[j]);
                mma_bf16(acc[1][j], AhF[1], BF[j]);
            }
#pragma unroll
            for (int j = 0; j < 8; j++) {
                mma_bf16(acc[0][j], AlF[0], BF[j]);
                mma_bf16(acc[1][j], AlF[1], BF[j]);
            }
#pragma unroll
            for (int j = 0; j < 8; j++) {
                const uint32_t nb = bbase + 3 * MATB
                                  + (uint32_t)((c0 + j * 8 + lr) * PSTR) * 2 + kofs;
                BF[j][0] = lds32(nb);
                BF[j][1] = lds32(nb + 16);
            }
#pragma unroll
            for (int j = 0; j < 8; j++) {
                mma_bf16(acc[0][j], AhF[0], BF[j]);
                mma_bf16(acc[1][j], AhF[1], BF[j]);
            }
        }
    }

    // epilogue: bias + (optional) permuted scatter / hi-lo split
#pragma unroll
    for (int i = 0; i < 2; i++) {
        const int mrow = m0 + r0 + i * 16 + lr;
#pragma unroll
        for (int half = 0; half < 2; half++) {
            const int m = mrow + half * 8;
            const size_t orow = (MODE == 3) ? (size_t)perm_row(m) : (size_t)m;
#pragma unroll
            for (int j = 0; j < 8; j++) {
                const int col = n0 + c0 + j * 8 + lq * 2;
                const float2 bb = *(const float2*)(bg + col);
                const float x0 = acc[i][j][half * 2 + 0] + bb.x;
                const float x1 = acc[i][j][half * 2 + 1] + bb.y;
                if (HL) {
                    __nv_bfloat16 h0, l0, h1, l1;
                    split1(x0, h0, l0); split1(x1, h1, l1);
                    *(uint32_t*)(outH + orow * kE + col) = pk(h0, h1);
                    *(uint32_t*)(outL + orow * kE + col) = pk(l0, l1);
                } else {
                    *(float2*)(outF + orow * kE + col) = make_float2(x0, x1);
                }
            }
        }
    }
}

// ---------------- fused flash attention (fp32, hi/lo epilogue) ---------------
__global__ __launch_bounds__(256, 2)
void attn_kernel() {
    extern __shared__ char s_raw[];
    float* sm = (float*)s_raw;
    float* sQ = sm;                    // 64*132
    float* sK = sQ + 64 * 132;         // 64*68
    float* sV = sK + 64 * 68;          // 64*68
    float* sP = sV + 64 * 68;          // 128*68

    const int tid = threadIdx.x;
    const int y = blockIdx.y;
    const int b = y / (kG * kH);
    const int g = (y / kH) & 3;
    const int h = y % kH;
    const int q0 = blockIdx.x * 128;

    const size_t head_q  = ((size_t)(b * kG + g) * kT) * kE + h * kD;
    const size_t head_kv = ((size_t)(b * kG + g) * kS) * kE + h * kD;

#pragma unroll
    for (int it = 0; it < 8; ++it) {
        const int idx = tid + 256 * it;
        const int r = idx >> 4;
        const int d4 = (idx & 15) * 4;
        const float4 q4 = *(const float4*)(g_qi + head_q + (size_t)(q0 + r) * kE + d4);
        sQ[(d4 + 0) * 132 + r] = q4.x * 0.125f;
        sQ[(d4 + 1) * 132 + r] = q4.y * 0.125f;
        sQ[(d4 + 2) * 132 + r] = q4.z * 0.125f;
        sQ[(d4 + 3) * 132 + r] = q4.w * 0.125f;
    }

    const int tr = tid >> 4;
    const int tc = tid & 15;

    float m_i[8], l_i[8], o[8][4];
#pragma unroll
    for (int i = 0; i < 8; i++) {
        m_i[i] = -1e30f; l_i[i] = 0.f;
#pragma unroll
        for (int j = 0; j < 4; j++) o[i][j] = 0.f;
    }

    for (int kv = 0; kv < kS; kv += 64) {
        __syncthreads();
#pragma unroll
        for (int it = 0; it < 4; ++it) {
            const int idx = tid + 256 * it;
            const int s = idx >> 4;
            const int d4 = (idx & 15) * 4;
            const float4 k4 = *(const float4*)(g_ki + head_kv + (size_t)(kv + s) * kE + d4);
            sK[(d4 + 0) * 68 + s] = k4.x;
            sK[(d4 + 1) * 68 + s] = k4.y;
            sK[(d4 + 2) * 68 + s] = k4.z;
            sK[(d4 + 3) * 68 + s] = k4.w;
            const float4 v4 = *(const float4*)(g_vi + head_kv + (size_t)(kv + s) * kE + d4);
            *(float4*)&sV[s * 68 + d4] = v4;
        }
        __syncthreads();

        float acc[8][4];
#pragma unroll
        for (int i = 0; i < 8; i++)
#pragma unroll
            for (int j = 0; j < 4; j++) acc[i][j] = 0.f;

#pragma unroll 4
        for (int d = 0; d < 64; ++d) {
            const float4 a0 = *(const float4*)&sQ[d * 132 + tr * 8];
            const float4 a1 = *(const float4*)&sQ[d * 132 + tr * 8 + 4];
            const float4 kb = *(const float4*)&sK[d * 68 + tc * 4];
            const float av[8] = {a0.x, a0.y, a0.z, a0.w, a1.x, a1.y, a1.z, a1.w};
#pragma unroll
            for (int i = 0; i < 8; i++) {
                acc[i][0] += av[i] * kb.x;
                acc[i][1] += av[i] * kb.y;
                acc[i][2] += av[i] * kb.z;
                acc[i][3] += av[i] * kb.w;
            }
        }

#pragma unroll
        for (int i = 0; i < 8; i++) {
            float mt = fmaxf(fmaxf(acc[i][0], acc[i][1]), fmaxf(acc[i][2], acc[i][3]));
            mt = fmaxf(mt, __shfl_xor_sync(0xffffffffu, mt, 1));
            mt = fmaxf(mt, __shfl_xor_sync(0xffffffffu, mt, 2));
            mt = fmaxf(mt, __shfl_xor_sync(0xffffffffu, mt, 4));
            mt = fmaxf(mt, __shfl_xor_sync(0xffffffffu, mt, 8));
            const float mnew = fmaxf(m_i[i], mt);
            const float corr = __expf(m_i[i] - mnew);
            const float p0 = __expf(acc[i][0] - mnew);
            const float p1 = __expf(acc[i][1] - mnew);
            const float p2 = __expf(acc[i][2] - mnew);
            const float p3 = __expf(acc[i][3] - mnew);
            float rs = (p0 + p1) + (p2 + p3);
            rs += __shfl_xor_sync(0xffffffffu, rs, 1);
            rs += __shfl_xor_sync(0xffffffffu, rs, 2);
            rs += __shfl_xor_sync(0xffffffffu, rs, 4);
            rs += __shfl_xor_sync(0xffffffffu, rs, 8);
            l_i[i] = l_i[i] * corr + rs;
            m_i[i] = mnew;
            o[i][0] *= corr; o[i][1] *= corr; o[i][2] *= corr; o[i][3] *= corr;
            *(float4*)&sP[(tr * 8 + i) * 68 + tc * 4] = make_float4(p0, p1, p2, p3);
        }
        __syncthreads();

#pragma unroll 1
        for (int s4 = 0; s4 < 64; s4 += 4) {
            float4 pv[8];
#pragma unroll
            for (int i = 0; i < 8; i++)
                pv[i] = *(const float4*)&sP[(tr * 8 + i) * 68 + s4];
#pragma unroll
            for (int u = 0; u < 4; u++) {
                const float4 vb = *(const float4*)&sV[(s4 + u) * 68 + tc * 4];
#pragma unroll
                for (int i = 0; i < 8; i++) {
                    const float p = (u == 0) ? pv[i].x : (u == 1) ? pv[i].y
                                  : (u == 2) ? pv[i].z : pv[i].w;
                    o[i][0] += p * vb.x;
                    o[i][1] += p * vb.y;
                    o[i][2] += p * vb.z;
                    o[i][3] += p * vb.w;
                }
            }
        }
    }

    // epilogue: normalize, hi/lo split, write a_c_h / a_c_l (bf16)
#pragma unroll
    for (int i = 0; i < 8; i++) {
        const float inv = 1.0f / l_i[i];
        const float v0 = o[i][0] * inv, v1 = o[i][1] * inv;
        const float v2 = o[i][2] * inv, v3 = o[i][3] * inv;
        __nv_bfloat16 h0, l0, h1, l1, h2, l2, h3, l3;
        split1(v0, h0, l0); split1(v1, h1, l1);
        split1(v2, h2, l2); split1(v3, h3, l3);
        const size_t off = head_q + (size_t)(q0 + tr * 8 + i) * kE + tc * 4;
        *(uint2*)(a_c_h + off) = make_uint2(pk(h0, h1), pk(h2, h3));
        *(uint2*)(a_c_l + off) = make_uint2(pk(l0, l1), pk(l2, l3));
    }
}

// ---------------- launch ----------------------------------------------------
extern "C" void kernel_launch(void* const* d_in, const int* in_sizes, int n_in,
                              void* d_out, int out_size) {
    const float* query = (const float*)d_in[0];
    const float* key   = (const float*)d_in[1];
    const float* value = (const float*)d_in[2];
    const float* Wqg   = (const float*)d_in[3];
    const float* bqg   = (const float*)d_in[4];
    const float* Wk    = (const float*)d_in[5];
    const float* bk    = (const float*)d_in[6];
    const float* Wv    = (const float*)d_in[7];
    const float* bv    = (const float*)d_in[8];
    const float* Wq_in = (const float*)d_in[9];
    const float* bq_in = (const float*)d_in[10];
    const float* Wk_in = (const float*)d_in[11];
    const float* bk_in = (const float*)d_in[12];
    const float* Wv_in = (const float*)d_in[13];
    const float* bv_in = (const float*)d_in[14];
    const float* Wout  = (const float*)d_in[15];
    const float* bout  = (const float*)d_in[16];

#define SYM(p, s) void* p; cudaGetSymbolAddress(&p, s)
    SYM(p_cq_h, c_q_h); SYM(p_cq_l, c_q_l);
    SYM(p_ck_h, c_k_h); SYM(p_ck_l, c_k_l);
    SYM(p_cv_h, c_v_h); SYM(p_cv_l, c_v_l);
    SYM(p_aq_h, a_q_h); SYM(p_aq_l, a_q_l);
    SYM(p_ak_h, a_k_h); SYM(p_ak_l, a_k_l);
    SYM(p_ax_h, a_x_h); SYM(p_ax_l, a_x_l);
    SYM(p_ac_h, a_c_h); SYM(p_ac_l, a_c_l);
    SYM(p_w0_h, w0_h);  SYM(p_w0_l, w0_l);
    SYM(p_w1_h, w1_h);  SYM(p_w1_l, w1_l);
    SYM(p_w2_h, w2_h);  SYM(p_w2_l, w2_l);
    SYM(p_wq_h, wq_h);  SYM(p_wq_l, wq_l);
    SYM(p_wk_h, wk_h);  SYM(p_wk_l, wk_l);
    SYM(p_wv_h, wv_h);  SYM(p_wv_l, wv_l);
    SYM(p_wo_h, wo_h);  SYM(p_wo_l, wo_l);
    SYM(p_qi, g_qi); SYM(p_ki, g_ki); SYM(p_vi, g_vi);
#undef SYM

    cudaFuncSetAttribute(gemm_mma<0, true>,  cudaFuncAttributeMaxDynamicSharedMemorySize, kSmemGemm);
    cudaFuncSetAttribute(gemm_mma<1, false>, cudaFuncAttributeMaxDynamicSharedMemorySize, kSmemGemm);
    cudaFuncSetAttribute(gemm_mma<2, false>, cudaFuncAttributeMaxDynamicSharedMemorySize, kSmemGemm);
    cudaFuncSetAttribute(gemm_mma<3, false>, cudaFuncAttributeMaxDynamicSharedMemorySize, kSmemGemm);
    const int smem_attn = (64 * 132 + 64 * 68 + 64 * 68 + 128 * 68) * 4;  // 103424 B
    cudaFuncSetAttribute(attn_kernel, cudaFuncAttributeMaxDynamicSharedMemorySize, smem_attn);

    typedef const __nv_bfloat16* BP;
    typedef __nv_bfloat16* BPm;

    // hi/lo conversions: 3 inputs + 7 weights
    cvt_hl<<<kNSE / 4 / 256, 256>>>((const float4*)query, (uint2*)p_cq_h, (uint2*)p_cq_l, kNSE / 4);
    cvt_hl<<<kNSE / 4 / 256, 256>>>((const float4*)key,   (uint2*)p_ck_h, (uint2*)p_ck_l, kNSE / 4);
    cvt_hl<<<kNSE / 4 / 256, 256>>>((const float4*)value, (uint2*)p_cv_h, (uint2*)p_cv_l, kNSE / 4);
    cvt_hl<<<kEE  / 4 / 256, 256>>>((const float4*)Wqg,   (uint2*)p_w0_h, (uint2*)p_w0_l, kEE / 4);
    cvt_hl<<<kEE  / 4 / 256, 256>>>((const float4*)Wk,    (uint2*)p_w1_h, (uint2*)p_w1_l, kEE / 4);
    cvt_hl<<<kEE  / 4 / 256, 256>>>((const float4*)Wv,    (uint2*)p_w2_h, (uint2*)p_w2_l, kEE / 4);
    cvt_hl<<<kGEE / 4 / 256, 256>>>((const float4*)Wq_in, (uint2*)p_wq_h, (uint2*)p_wq_l, kGEE / 4);
    cvt_hl<<<kGEE / 4 / 256, 256>>>((const float4*)Wk_in, (uint2*)p_wk_h, (uint2*)p_wk_l, kGEE / 4);
    cvt_hl<<<kGEE / 4 / 256, 256>>>((const float4*)Wv_in, (uint2*)p_wv_h, (uint2*)p_wv_l, kGEE / 4);
    cvt_hl<<<kGEE / 4 / 256, 256>>>((const float4*)Wout,  (uint2*)p_wo_h, (uint2*)p_wo_l, kGEE / 4);

    const dim3 blk(256);
    // outer projections -> hi/lo outputs
    gemm_mma<0, true><<<dim3(6, 32), blk, kSmemGemm>>>(
        (BP)p_cq_h, (BP)p_cq_l, (BP)p_w0_h, (BP)p_w0_l, bqg, nullptr, (BPm)p_aq_h, (BPm)p_aq_l);
    gemm_mma<0, true><<<dim3(6, 32), blk, kSmemGemm>>>(
        (BP)p_ck_h, (BP)p_ck_l, (BP)p_w1_h, (BP)p_w1_l, bk, nullptr, (BPm)p_ak_h, (BPm)p_ak_l);
    gemm_mma<0, true><<<dim3(6, 32), blk, kSmemGemm>>>(
        (BP)p_cv_h, (BP)p_cv_l, (BP)p_w2_h, (BP)p_w2_l, bv, nullptr, (BPm)p_ax_h, (BPm)p_ax_l);
    // per-group in-projections -> fp32 (attention inputs)
    gemm_mma<1, false><<<dim3(6, 32), blk, kSmemGemm>>>(
        (BP)p_aq_h, (BP)p_aq_l, (BP)p_wq_h, (BP)p_wq_l, bq_in, (float*)p_qi, nullptr, nullptr);
    gemm_mma<2, false><<<dim3(6, 128), blk, kSmemGemm>>>(
        (BP)p_ak_h, (BP)p_ak_l, (BP)p_wk_h, (BP)p_wk_l, bk_in, (float*)p_ki, nullptr, nullptr);
    gemm_mma<2, false><<<dim3(6, 128), blk, kSmemGemm>>>(
        (BP)p_ax_h, (BP)p_ax_l, (BP)p_wv_h, (BP)p_wv_l, bv_in, (float*)p_vi, nullptr, nullptr);
    // fused flash attention (writes a_c hi/lo)
    attn_kernel<<<dim3(kT / 128, kB * kG * kH), blk, smem_attn>>>();
    // out-projection with scatter back to sequence order -> fp32 d_out
    gemm_mma<3, false><<<dim3(6, 32), blk, kSmemGemm>>>(
        (BP)p_ac_h, (BP)p_ac_l, (BP)p_wo_h, (BP)p_wo_l, bout, (float*)d_out, nullptr, nullptr);
}

// round 10
// speedup vs baseline: 2.1379x; 1.3643x over previous
#include <cuda_runtime.h>
#include <cuda_bf16.h>
#include <cstdint>

// GroupQueryAttention: B=2, S=2048, E=768, H=12, G=4, D=64, T=512
// Round 7: bf16x3 HMMA everywhere. GEMMs as round 6 (passing, ~300TF/s eff);
// attention rewritten on mma.sync m16n8k16 with register-resident P,
// split-precision QK (Qh*Kh+Ql*Kh+Qh*Kl) and PV (Ph*Vh+Pl*Vh+Ph*Vl).

constexpr int kE = 768;
constexpr int kB = 2;
constexpr int kS = 2048;
constexpr int kH = 12;
constexpr int kG = 4;
constexpr int kD = 64;
constexpr int kT = 512;                 // S / G
constexpr int kNSE = kB * kS * kE;      // 3,145,728
constexpr int kEE  = kE * kE;           // 589,824
constexpr int kGEE = kG * kE * kE;      // 2,359,296
constexpr int kGSE = kB * kG * kS * kE; // 12,582,912
constexpr int kQTE = kB * kG * kT * kE; // 3,145,728

// ---------------- scratch (device globals; no allocations allowed) ----------
__device__ __nv_bfloat16 c_q_h[kNSE], c_q_l[kNSE];   // query input hl
__device__ __nv_bfloat16 c_k_h[kNSE], c_k_l[kNSE];
__device__ __nv_bfloat16 c_v_h[kNSE], c_v_l[kNSE];
__device__ __nv_bfloat16 a_q_h[kNSE], a_q_l[kNSE];   // outer projections hl
__device__ __nv_bfloat16 a_k_h[kNSE], a_k_l[kNSE];
__device__ __nv_bfloat16 a_x_h[kNSE], a_x_l[kNSE];
__device__ __nv_bfloat16 a_qi_h[kQTE], a_qi_l[kQTE]; // q in-proj (pre-scaled)
__device__ __nv_bfloat16 a_ki_h[kGSE], a_ki_l[kGSE]; // k in-proj
__device__ __nv_bfloat16 a_vi_h[kGSE], a_vi_l[kGSE]; // v in-proj
__device__ __nv_bfloat16 a_c_h[kQTE], a_c_l[kQTE];   // attn context
__device__ __nv_bfloat16 w0_h[kEE],  w0_l[kEE];
__device__ __nv_bfloat16 w1_h[kEE],  w1_l[kEE];
__device__ __nv_bfloat16 w2_h[kEE],  w2_l[kEE];
__device__ __nv_bfloat16 wq_h[kGEE], wq_l[kGEE];
__device__ __nv_bfloat16 wk_h[kGEE], wk_l[kGEE];
__device__ __nv_bfloat16 wv_h[kGEE], wv_l[kGEE];
__device__ __nv_bfloat16 wo_h[kGEE], wo_l[kGEE];

// ---------------- helpers ----------------------------------------------------
__device__ __forceinline__ uint32_t smem_u32(const void* p) {
    uint32_t a;
    asm("{ .reg .u64 t; cvta.to.shared.u64 t, %1; cvt.u32.u64 %0, t; }"
        : "=r"(a) : "l"(p));
    return a;
}
__device__ __forceinline__ uint32_t lds32(uint32_t a) {
    uint32_t v;
    asm volatile("ld.shared.b32 %0, [%1];" : "=r"(v) : "r"(a));
    return v;
}
__device__ __forceinline__ void cp16(uint32_t dst, const void* src) {
    asm volatile("cp.async.cg.shared.global [%0], [%1], 16;" :: "r"(dst), "l"(src));
}
#define CP_COMMIT() asm volatile("cp.async.commit_group;" ::: "memory")
#define CP_WAIT0()  asm volatile("cp.async.wait_group 0;" ::: "memory")

__device__ __forceinline__ void mma_bf16(float* c, const uint32_t* a, const uint32_t* b) {
    asm volatile(
        "mma.sync.aligned.m16n8k16.row.col.f32.bf16.bf16.f32 "
        "{%0,%1,%2,%3}, {%4,%5,%6,%7}, {%8,%9}, {%0,%1,%2,%3};"
        : "+f"(c[0]), "+f"(c[1]), "+f"(c[2]), "+f"(c[3])
        : "r"(a[0]), "r"(a[1]), "r"(a[2]), "r"(a[3]), "r"(b[0]), "r"(b[1]));
}
__device__ __forceinline__ void ldsm4(uint32_t& r0, uint32_t& r1, uint32_t& r2,
                                      uint32_t& r3, uint32_t addr) {
    asm volatile("ldmatrix.sync.aligned.m8n8.x4.shared.b16 {%0,%1,%2,%3}, [%4];"
                 : "=r"(r0), "=r"(r1), "=r"(r2), "=r"(r3) : "r"(addr));
}
__device__ __forceinline__ void ldsm4t(uint32_t& r0, uint32_t& r1, uint32_t& r2,
                                       uint32_t& r3, uint32_t addr) {
    asm volatile("ldmatrix.sync.aligned.m8n8.x4.trans.shared.b16 {%0,%1,%2,%3}, [%4];"
                 : "=r"(r0), "=r"(r1), "=r"(r2), "=r"(r3) : "r"(addr));
}

__device__ __forceinline__ void split1(float x, __nv_bfloat16& h, __nv_bfloat16& l) {
    h = __float2bfloat16(x);
    l = __float2bfloat16(x - __bfloat162float(h));
}
__device__ __forceinline__ uint32_t pk(__nv_bfloat16 a, __nv_bfloat16 b) {
    uint16_t ua = *(uint16_t*)&a, ub = *(uint16_t*)&b;
    return (uint32_t)ua | ((uint32_t)ub << 16);
}

// ---------------- row mappings -----------------------------------------------
template <int MODE>
__device__ __forceinline__ int in_row(int m) {
    if (MODE == 1) {
        int b = m >> 11; int g = (m >> 9) & 3; int t = m & 511;
        return (b << 11) + (t << 2) + g;
    }
    if (MODE == 2) {
        int b = m >> 13; int s = m & 2047;
        return (b << 11) + s;
    }
    return m;
}
__device__ __forceinline__ int perm_row(int m) {
    int b = m >> 11; int g = (m >> 9) & 3; int t = m & 511;
    return (b << 11) + (t << 2) + g;
}

// ---------------- hi/lo conversion kernel ------------------------------------
__global__ void cvt_hl(const float4* __restrict__ in, uint2* __restrict__ h,
                       uint2* __restrict__ l, int n4) {
    int i = blockIdx.x * 256 + threadIdx.x;
    if (i >= n4) return;
    float4 v = in[i];
    __nv_bfloat16 h0, l0, h1, l1, h2, l2, h3, l3;
    split1(v.x, h0, l0); split1(v.y, h1, l1);
    split1(v.z, h2, l2); split1(v.w, h3, l3);
    h[i] = make_uint2(pk(h0, h1), pk(h2, h3));
    l[i] = make_uint2(pk(l0, l1), pk(l2, l3));
}

// ---------------- bf16x3 HMMA GEMM (round-6 verified core) -------------------
constexpr int PSTR = 40;               // padded row stride (bf16 elems)
constexpr int MATB = 128 * PSTR * 2;   // 10240 B per matrix
constexpr int BUFB = 4 * MATB;         // 40960 B per buffer (Ah|Al|Wh|Wl)
constexpr int kSmemGemm = 2 * BUFB;    // 81920 B

template <int MODE, int OUT>   // OUT: 0 = fp32, 1 = bf16 hi/lo (scaled)
__global__ __launch_bounds__(256, 2)
void gemm_mma(const __nv_bfloat16* __restrict__ Ah, const __nv_bfloat16* __restrict__ Al,
              const __nv_bfloat16* __restrict__ Wh, const __nv_bfloat16* __restrict__ Wl,
              const float* __restrict__ bias, float* __restrict__ outF,
              __nv_bfloat16* __restrict__ outH, __nv_bfloat16* __restrict__ outL,
              float scale) {
    extern __shared__ char s_raw[];
    const uint32_t sb = smem_u32(s_raw);

    const int tid = threadIdx.x;
    const int m0 = blockIdx.y * 128;
    const int n0 = blockIdx.x * 128;

    int g = 0;
    if (MODE == 1 || MODE == 3) g = (m0 >> 9) & 3;
    if (MODE == 2)              g = (m0 >> 11) & 3;
    const __nv_bfloat16* WgH = Wh + (size_t)g * kEE;
    const __nv_bfloat16* WgL = Wl + (size_t)g * kEE;
    const float* bg = bias + (size_t)g * kE;

    const int lrow = tid >> 1;
    const int lhalf = tid & 1;
    const int arow = in_row<MODE>(m0 + lrow);
    const __nv_bfloat16* pAh = Ah  + (size_t)arow * kE + lhalf * 16;
    const __nv_bfloat16* pAl = Al  + (size_t)arow * kE + lhalf * 16;
    const __nv_bfloat16* pWh = WgH + (size_t)(n0 + lrow) * kE + lhalf * 16;
    const __nv_bfloat16* pWl = WgL + (size_t)(n0 + lrow) * kE + lhalf * 16;
    const uint32_t sdst = sb + (uint32_t)(lrow * PSTR + lhalf * 16) * 2;

    const int lane = tid & 31;
    const int wid = tid >> 5;
    const int r0 = (wid & 3) * 32;
    const int c0 = (wid >> 2) * 64;
    const int lr = lane >> 2;
    const int lq = lane & 3;

    float acc[2][8][4];
#pragma unroll
    for (int i = 0; i < 2; i++)
#pragma unroll
        for (int j = 0; j < 8; j++)
#pragma unroll
            for (int q = 0; q < 4; q++) acc[i][j][q] = 0.f;

    {
        cp16(sdst,            pAh); cp16(sdst + 16,            pAh + 8);
        cp16(sdst + MATB,     pAl); cp16(sdst + MATB + 16,     pAl + 8);
        cp16(sdst + 2 * MATB, pWh); cp16(sdst + 2 * MATB + 16, pWh + 8);
        cp16(sdst + 3 * MATB, pWl); cp16(sdst + 3 * MATB + 16, pWl + 8);
        CP_COMMIT();
    }

#pragma unroll 1
    for (int p = 0; p < 24; ++p) {
        CP_WAIT0();
        __syncthreads();
        if (p + 1 < 24) {
            const int go = (p + 1) * 32;
            const uint32_t d = sdst + ((p + 1) & 1) * BUFB;
            cp16(d,            pAh + go); cp16(d + 16,            pAh + go + 8);
            cp16(d + MATB,     pAl + go); cp16(d + MATB + 16,     pAl + go + 8);
            cp16(d + 2 * MATB, pWh + go); cp16(d + 2 * MATB + 16, pWh + go + 8);
            cp16(d + 3 * MATB, pWl + go); cp16(d + 3 * MATB + 16, pWl + go + 8);
            CP_COMMIT();
        }

        const uint32_t bbase = sb + (p & 1) * BUFB;
#pragma unroll
        for (int ks = 0; ks < 2; ++ks) {
            const uint32_t kofs = (uint32_t)(ks * 16 + lq * 2) * 2;
            uint32_t AhF[2][4], AlF[2][4], BF[8][2];
#pragma unroll
            for (int i = 0; i < 2; i++) {
                const uint32_t ab = bbase + (uint32_t)((r0 + i * 16 + lr) * PSTR) * 2 + kofs;
                AhF[i][0] = lds32(ab);
                AhF[i][1] = lds32(ab + 8 * PSTR * 2);
                AhF[i][2] = lds32(ab + 16);
                AhF[i][3] = lds32(ab + 8 * PSTR * 2 + 16);
                const uint32_t al = ab + MATB;
                AlF[i][0] = lds32(al);
                AlF[i][1] = lds32(al + 8 * PSTR * 2);
                AlF[i][2] = lds32(al + 16);
                AlF[i][3] = lds32(al + 8 * PSTR * 2 + 16);
            }
#pragma unroll
            for (int j = 0; j < 8; j++) {
                const uint32_t nb = bbase + 2 * MATB
                                  + (uint32_t)((c0 + j * 8 + lr) * PSTR) * 2 + kofs;
                BF[j][0] = lds32(nb);
                BF[j][1] = lds32(nb + 16);
            }
#pragma unroll
            for (int j = 0; j < 8; j++) {
                mma_bf16(acc[0][j], AhF[0], BF[j]);
                mma_bf16(acc[1][j], AhF[1], BF[j]);
            }
#pragma unroll
            for (int j = 0; j < 8; j++) {
                mma_bf16(acc[0][j], AlF[0], BF[j]);
                mma_bf16(acc[1][j], AlF[1], BF[j]);
            }
#pragma unroll
            for (int j = 0; j < 8; j++) {
                const uint32_t nb = bbase + 3 * MATB
                                  + (uint32_t)((c0 + j * 8 + lr) * PSTR) * 2 + kofs;
                BF[j][0] = lds32(nb);
                BF[j][1] = lds32(nb + 16);
            }
#pragma unroll
            for (int j = 0; j < 8; j++) {
                mma_bf16(acc[0][j], AhF[0], BF[j]);
                mma_bf16(acc[1][j], AhF[1], BF[j]);
            }
        }
    }

#pragma unroll
    for (int i = 0; i < 2; i++) {
#pragma unroll
        for (int half = 0; half < 2; half++) {
            const int m = m0 + r0 + i * 16 + lr + half * 8;
            const size_t orow = (MODE == 3) ? (size_t)perm_row(m) : (size_t)m;
#pragma unroll
            for (int j = 0; j < 8; j++) {
                const int col = n0 + c0 + j * 8 + lq * 2;
                const float2 bb = *(const float2*)(bg + col);
                float x0 = acc[i][j][half * 2 + 0] + bb.x;
                float x1 = acc[i][j][half * 2 + 1] + bb.y;
                if (OUT == 1) {
                    x0 *= scale; x1 *= scale;
                    __nv_bfloat16 h0, l0, h1, l1;
                    split1(x0, h0, l0); split1(x1, h1, l1);
                    *(uint32_t*)(outH + orow * kE + col) = pk(h0, h1);
                    *(uint32_t*)(outL + orow * kE + col) = pk(l0, l1);
                } else {
                    *(float2*)(outF + orow * kE + col) = make_float2(x0, x1);
                }
            }
        }
    }
}

// ---------------- HMMA flash attention ---------------------------------------
// grid (T/128, B*G*H), 256 threads (8 warps). Warp w: q rows w*16..w*16+15.
// BKV=64. K,V tiles in smem [s][d] bf16 hi/lo, stride 72 (144B, LDSM-clean).
// P stays in registers: QK acc -> exp/split -> PV A-frags (layout identity).
constexpr int ASTR = 72;   // smem row stride in bf16 elems

__global__ __launch_bounds__(256, 2)
void attn_mma() {
    __shared__ __align__(16) uint16_t sKh[64 * ASTR], sKl[64 * ASTR];
    __shared__ __align__(16) uint16_t sVh[64 * ASTR], sVl[64 * ASTR];

    const int tid = threadIdx.x;
    const int wid = tid >> 5;
    const int lane = tid & 31;
    const int lr = lane >> 2;
    const int lq = lane & 3;

    const int y = blockIdx.y;
    const int b = y / (kG * kH);
    const int g = (y / kH) & 3;
    const int h = y % kH;
    const int q0 = blockIdx.x * 128;

    const size_t head_q  = ((size_t)(b * kG + g) * kT) * kE + h * kD;
    const size_t head_kv = ((size_t)(b * kG + g) * kS) * kE + h * kD;

    // Q fragments (held in registers for the whole kernel); q pre-scaled.
    uint32_t qh[4][4], ql[4][4];
    {
        const size_t r0o = head_q + (size_t)(q0 + wid * 16 + lr) * kE;
        const size_t r1o = r0o + 8 * kE;
#pragma unroll
        for (int kc = 0; kc < 4; kc++) {
            const int cA = kc * 16 + lq * 2;
            qh[kc][0] = *(const uint32_t*)(a_qi_h + r0o + cA);
            qh[kc][1] = *(const uint32_t*)(a_qi_h + r1o + cA);
            qh[kc][2] = *(const uint32_t*)(a_qi_h + r0o + cA + 8);
            qh[kc][3] = *(const uint32_t*)(a_qi_h + r1o + cA + 8);
            ql[kc][0] = *(const uint32_t*)(a_qi_l + r0o + cA);
            ql[kc][1] = *(const uint32_t*)(a_qi_l + r1o + cA);
            ql[kc][2] = *(const uint32_t*)(a_qi_l + r0o + cA + 8);
            ql[kc][3] = *(const uint32_t*)(a_qi_l + r1o + cA + 8);
        }
    }

    // per-lane ldmatrix address component (shared by K and V-trans loads)
    const uint32_t lko = (uint32_t)((((lane >> 3) & 1) * 8 + (lane & 7)) * ASTR * 2
                                    + (lane >> 4) * 16);
    const uint32_t bKh = smem_u32(sKh), bKl = smem_u32(sKl);
    const uint32_t bVh = smem_u32(sVh), bVl = smem_u32(sVl);

    float o[8][4];
#pragma unroll
    for (int j = 0; j < 8; j++)
#pragma unroll
        for (int e = 0; e < 4; e++) o[j][e] = 0.f;
    float m0 = -1e30f, m1 = -1e30f, l0 = 0.f, l1 = 0.f;

    // tile-load addressing: thread -> (row, 16-col chunk)
    const int trow = tid >> 2;
    const int tcol = (tid & 3) * 16;
    const uint32_t sof = (uint32_t)(trow * ASTR + tcol) * 2;

#pragma unroll 1
    for (int kv = 0; kv < kS; kv += 64) {
        {
            const size_t gofs = head_kv + (size_t)(kv + trow) * kE + tcol;
            *(uint4*)((char*)sKh + sof)      = *(const uint4*)(a_ki_h + gofs);
            *(uint4*)((char*)sKh + sof + 16) = *(const uint4*)(a_ki_h + gofs + 8);
            *(uint4*)((char*)sKl + sof)      = *(const uint4*)(a_ki_l + gofs);
            *(uint4*)((char*)sKl + sof + 16) = *(const uint4*)(a_ki_l + gofs + 8);
            *(uint4*)((char*)sVh + sof)      = *(const uint4*)(a_vi_h + gofs);
            *(uint4*)((char*)sVh + sof + 16) = *(const uint4*)(a_vi_h + gofs + 8);
            *(uint4*)((char*)sVl + sof)      = *(const uint4*)(a_vi_l + gofs);
            *(uint4*)((char*)sVl + sof + 16) = *(const uint4*)(a_vi_l + gofs + 8);
        }
        __syncthreads();

        // ---- QK: acc[128x64] in 8 n-tiles per warp ----
        float acc[8][4];
#pragma unroll
        for (int j = 0; j < 8; j++)
#pragma unroll
            for (int e = 0; e < 4; e++) acc[j][e] = 0.f;

#pragma unroll
        for (int kc = 0; kc < 4; kc++) {
            uint32_t kb[8][2];
#pragma unroll
            for (int u = 0; u < 4; u++) {
                uint32_t r0, r1, r2, r3;
                ldsm4(r0, r1, r2, r3, bKh + (uint32_t)(u * 16 * ASTR + kc * 16) * 2 + lko);
                kb[2 * u][0] = r0; kb[2 * u][1] = r2;
                kb[2 * u + 1][0] = r1; kb[2 * u + 1][1] = r3;
            }
#pragma unroll
            for (int j = 0; j < 8; j++) mma_bf16(acc[j], qh[kc], kb[j]);
#pragma unroll
            for (int j = 0; j < 8; j++) mma_bf16(acc[j], ql[kc], kb[j]);
#pragma unroll
            for (int u = 0; u < 4; u++) {
                uint32_t r0, r1, r2, r3;
                ldsm4(r0, r1, r2, r3, bKl + (uint32_t)(u * 16 * ASTR + kc * 16) * 2 + lko);
                kb[2 * u][0] = r0; kb[2 * u][1] = r2;
                kb[2 * u + 1][0] = r1; kb[2 * u + 1][1] = r3;
            }
#pragma unroll
            for (int j = 0; j < 8; j++) mma_bf16(acc[j], qh[kc], kb[j]);
        }

        // ---- online softmax (rows lr and lr+8) ----
        float mt0 = -1e30f, mt1 = -1e30f;
#pragma unroll
        for (int j = 0; j < 8; j++) {
            mt0 = fmaxf(mt0, fmaxf(acc[j][0], acc[j][1]));
            mt1 = fmaxf(mt1, fmaxf(acc[j][2], acc[j][3]));
        }
        mt0 = fmaxf(mt0, __shfl_xor_sync(0xffffffffu, mt0, 1));
        mt0 = fmaxf(mt0, __shfl_xor_sync(0xffffffffu, mt0, 2));
        mt1 = fmaxf(mt1, __shfl_xor_sync(0xffffffffu, mt1, 1));
        mt1 = fmaxf(mt1, __shfl_xor_sync(0xffffffffu, mt1, 2));
        const float mn0 = fmaxf(m0, mt0);
        const float mn1 = fmaxf(m1, mt1);
        const float cr0 = __expf(m0 - mn0);
        const float cr1 = __expf(m1 - mn1);
        m0 = mn0; m1 = mn1;
        l0 *= cr0; l1 *= cr1;
#pragma unroll
        for (int j = 0; j < 8; j++) {
            o[j][0] *= cr0; o[j][1] *= cr0;
            o[j][2] *= cr1; o[j][3] *= cr1;
        }

        // exp + hi/lo split into PV A-fragments (pure layout identity)
        uint32_t pha[4][4], pla[4][4];
#pragma unroll
        for (int j = 0; j < 8; j++) {
            const float p0 = __expf(acc[j][0] - m0);
            const float p1 = __expf(acc[j][1] - m0);
            const float p2 = __expf(acc[j][2] - m1);
            const float p3 = __expf(acc[j][3] - m1);
            l0 += p0 + p1; l1 += p2 + p3;
            __nv_bfloat16 h0, e0, h1, e1, h2, e2, h3, e3;
            split1(p0, h0, e0); split1(p1, h1, e1);
            split1(p2, h2, e2); split1(p3, h3, e3);
            const int sc = j >> 1, hh = (j & 1) * 2;
            pha[sc][hh + 0] = pk(h0, h1); pha[sc][hh + 1] = pk(h2, h3);
            pla[sc][hh + 0] = pk(e0, e1); pla[sc][hh + 1] = pk(e2, e3);
        }

        // ---- PV: O += P.V (V via ldmatrix.trans on [s][d]) ----
#pragma unroll
        for (int sc = 0; sc < 4; sc++) {
            uint32_t vb[8][2];
#pragma unroll
            for (int u = 0; u < 4; u++) {
                uint32_t r0, r1, r2, r3;
                ldsm4t(r0, r1, r2, r3, bVh + (uint32_t)(sc * 16 * ASTR + u * 16) * 2 + lko);
                vb[2 * u][0] = r0; vb[2 * u][1] = r1;
                vb[2 * u + 1][0] = r2; vb[2 * u + 1][1] = r3;
            }
#pragma unroll
            for (int j = 0; j < 8; j++) mma_bf16(o[j], pha[sc], vb[j]);
#pragma unroll
            for (int j = 0; j < 8; j++) mma_bf16(o[j], pla[sc], vb[j]);
#pragma unroll
            for (int u = 0; u < 4; u++) {
                uint32_t r0, r1, r2, r3;
                ldsm4t(r0, r1, r2, r3, bVl + (uint32_t)(sc * 16 * ASTR + u * 16) * 2 + lko);
                vb[2 * u][0] = r0; vb[2 * u][1] = r1;
                vb[2 * u + 1][0] = r2; vb[2 * u + 1][1] = r3;
            }
#pragma unroll
            for (int j = 0; j < 8; j++) mma_bf16(o[j], pha[sc], vb[j]);
        }
        __syncthreads();
    }

    // ---- epilogue: normalize, hi/lo split, write a_c ----
    l0 += __shfl_xor_sync(0xffffffffu, l0, 1);
    l0 += __shfl_xor_sync(0xffffffffu, l0, 2);
    l1 += __shfl_xor_sync(0xffffffffu, l1, 1);
    l1 += __shfl_xor_sync(0xffffffffu, l1, 2);
    const float inv0 = 1.0f / l0, inv1 = 1.0f / l1;
    const size_t r0o = head_q + (size_t)(q0 + wid * 16 + lr) * kE;
    const size_t r1o = r0o + 8 * kE;
#pragma unroll
    for (int j = 0; j < 8; j++) {
        const int col = j * 8 + lq * 2;
        __nv_bfloat16 h0, e0, h1, e1;
        split1(o[j][0] * inv0, h0, e0); split1(o[j][1] * inv0, h1, e1);
        *(uint32_t*)(a_c_h + r0o + col) = pk(h0, h1);
        *(uint32_t*)(a_c_l + r0o + col) = pk(e0, e1);
        split1(o[j][2] * inv1, h0, e0); split1(o[j][3] * inv1, h1, e1);
        *(uint32_t*)(a_c_h + r1o + col) = pk(h0, h1);
        *(uint32_t*)(a_c_l + r1o + col) = pk(e0, e1);
    }
}

// ---------------- launch ----------------------------------------------------
extern "C" void kernel_launch(void* const* d_in, const int* in_sizes, int n_in,
                              void* d_out, int out_size) {
    const float* query = (const float*)d_in[0];
    const float* key   = (const float*)d_in[1];
    const float* value = (const float*)d_in[2];
    const float* Wqg   = (const float*)d_in[3];
    const float* bqg   = (const float*)d_in[4];
    const float* Wk    = (const float*)d_in[5];
    const float* bk    = (const float*)d_in[6];
    const float* Wv    = (const float*)d_in[7];
    const float* bv    = (const float*)d_in[8];
    const float* Wq_in = (const float*)d_in[9];
    const float* bq_in = (const float*)d_in[10];
    const float* Wk_in = (const float*)d_in[11];
    const float* bk_in = (const float*)d_in[12];
    const float* Wv_in = (const float*)d_in[13];
    const float* bv_in = (const float*)d_in[14];
    const float* Wout  = (const float*)d_in[15];
    const float* bout  = (const float*)d_in[16];

#define SYM(p, s) void* p; cudaGetSymbolAddress(&p, s)
    SYM(p_cq_h, c_q_h); SYM(p_cq_l, c_q_l);
    SYM(p_ck_h, c_k_h); SYM(p_ck_l, c_k_l);
    SYM(p_cv_h, c_v_h); SYM(p_cv_l, c_v_l);
    SYM(p_aq_h, a_q_h); SYM(p_aq_l, a_q_l);
    SYM(p_ak_h, a_k_h); SYM(p_ak_l, a_k_l);
    SYM(p_ax_h, a_x_h); SYM(p_ax_l, a_x_l);
    SYM(p_qi_h, a_qi_h); SYM(p_qi_l, a_qi_l);
    SYM(p_ki_h, a_ki_h); SYM(p_ki_l, a_ki_l);
    SYM(p_vi_h, a_vi_h); SYM(p_vi_l, a_vi_l);
    SYM(p_ac_h, a_c_h); SYM(p_ac_l, a_c_l);
    SYM(p_w0_h, w0_h);  SYM(p_w0_l, w0_l);
    SYM(p_w1_h, w1_h);  SYM(p_w1_l, w1_l);
    SYM(p_w2_h, w2_h);  SYM(p_w2_l, w2_l);
    SYM(p_wq_h, wq_h);  SYM(p_wq_l, wq_l);
    SYM(p_wk_h, wk_h);  SYM(p_wk_l, wk_l);
    SYM(p_wv_h, wv_h);  SYM(p_wv_l, wv_l);
    SYM(p_wo_h, wo_h);  SYM(p_wo_l, wo_l);
#undef SYM

    cudaFuncSetAttribute(gemm_mma<0, 1>, cudaFuncAttributeMaxDynamicSharedMemorySize, kSmemGemm);
    cudaFuncSetAttribute(gemm_mma<1, 1>, cudaFuncAttributeMaxDynamicSharedMemorySize, kSmemGemm);
    cudaFuncSetAttribute(gemm_mma<2, 1>, cudaFuncAttributeMaxDynamicSharedMemorySize, kSmemGemm);
    cudaFuncSetAttribute(gemm_mma<3, 0>, cudaFuncAttributeMaxDynamicSharedMemorySize, kSmemGemm);

    typedef const __nv_bfloat16* BP;
    typedef __nv_bfloat16* BPm;

    cvt_hl<<<kNSE / 4 / 256, 256>>>((const float4*)query, (uint2*)p_cq_h, (uint2*)p_cq_l, kNSE / 4);
    cvt_hl<<<kNSE / 4 / 256, 256>>>((const float4*)key,   (uint2*)p_ck_h, (uint2*)p_ck_l, kNSE / 4);
    cvt_hl<<<kNSE / 4 / 256, 256>>>((const float4*)value, (uint2*)p_cv_h, (uint2*)p_cv_l, kNSE / 4);
    cvt_hl<<<kEE  / 4 / 256, 256>>>((const float4*)Wqg,   (uint2*)p_w0_h, (uint2*)p_w0_l, kEE / 4);
    cvt_hl<<<kEE  / 4 / 256, 256>>>((const float4*)Wk,    (uint2*)p_w1_h, (uint2*)p_w1_l, kEE / 4);
    cvt_hl<<<kEE  / 4 / 256, 256>>>((const float4*)Wv,    (uint2*)p_w2_h, (uint2*)p_w2_l, kEE / 4);
    cvt_hl<<<kGEE / 4 / 256, 256>>>((const float4*)Wq_in, (uint2*)p_wq_h, (uint2*)p_wq_l, kGEE / 4);
    cvt_hl<<<kGEE / 4 / 256, 256>>>((const float4*)Wk_in, (uint2*)p_wk_h, (uint2*)p_wk_l, kGEE / 4);
    cvt_hl<<<kGEE / 4 / 256, 256>>>((const float4*)Wv_in, (uint2*)p_wv_h, (uint2*)p_wv_l, kGEE / 4);
    cvt_hl<<<kGEE / 4 / 256, 256>>>((const float4*)Wout,  (uint2*)p_wo_h, (uint2*)p_wo_l, kGEE / 4);

    const dim3 blk(256);
    // outer projections -> hi/lo
    gemm_mma<0, 1><<<dim3(6, 32), blk, kSmemGemm>>>(
        (BP)p_cq_h, (BP)p_cq_l, (BP)p_w0_h, (BP)p_w0_l, bqg,
        nullptr, (BPm)p_aq_h, (BPm)p_aq_l, 1.0f);
    gemm_mma<0, 1><<<dim3(6, 32), blk, kSmemGemm>>>(
        (BP)p_ck_h, (BP)p_ck_l, (BP)p_w1_h, (BP)p_w1_l, bk,
        nullptr, (BPm)p_ak_h, (BPm)p_ak_l, 1.0f);
    gemm_mma<0, 1><<<dim3(6, 32), blk, kSmemGemm>>>(
        (BP)p_cv_h, (BP)p_cv_l, (BP)p_w2_h, (BP)p_w2_l, bv,
        nullptr, (BPm)p_ax_h, (BPm)p_ax_l, 1.0f);
    // per-group in-projections -> hi/lo bf16 (q pre-scaled by 1/sqrt(D))
    gemm_mma<1, 1><<<dim3(6, 32), blk, kSmemGemm>>>(
        (BP)p_aq_h, (BP)p_aq_l, (BP)p_wq_h, (BP)p_wq_l, bq_in,
        nullptr, (BPm)p_qi_h, (BPm)p_qi_l, 0.125f);
    gemm_mma<2, 1><<<dim3(6, 128), blk, kSmemGemm>>>(
        (BP)p_ak_h, (BP)p_ak_l, (BP)p_wk_h, (BP)p_wk_l, bk_in,
        nullptr, (BPm)p_ki_h, (BPm)p_ki_l, 1.0f);
    gemm_mma<2, 1><<<dim3(6, 128), blk, kSmemGemm>>>(
        (BP)p_ax_h, (BP)p_ax_l, (BP)p_wv_h, (BP)p_wv_l, bv_in,
        nullptr, (BPm)p_vi_h, (BPm)p_vi_l, 1.0f);
    // HMMA flash attention (writes a_c hi/lo)
    attn_mma<<<dim3(kT / 128, kB * kG * kH), blk>>>();
    // out-projection with scatter back to sequence order -> fp32 d_out
    gemm_mma<3, 0><<<dim3(6, 32), blk, kSmemGemm>>>(
        (BP)p_ac_h, (BP)p_ac_l, (BP)p_wo_h, (BP)p_wo_l, bout,
        (float*)d_out, nullptr, nullptr, 1.0f);
}